// round 1
// baseline (speedup 1.0000x reference)
#include <cuda_runtime.h>
#include <math.h>

// Problem constants
#define NB 32
#define NN 512      // H == W == 512
#define NC 3

// -------- device globals (no allocation allowed) --------
__device__ __align__(128) float g_D [NN * NN];   // D[k][h]
__device__ __align__(128) float g_Dt[NN * NN];   // Dt[w][l] = D[l][w]
__device__ __align__(128) float g_t [(size_t)NB * NN * NN * NC];  // scratch y1[b,k,w,c]

// -------- init: DCT-II matrix, exact-argument cospi --------
// D[k,n] = cos(pi*(2n+1)*k/(2N)) * sqrt(2/N);  row 0 *= 1/sqrt(2)
// sqrt(2/512) = 1/16 exactly.  angle period: (2n+1)k mod 4N = mod 2048.
__global__ void init_dct_kernel() {
    int idx = blockIdx.x * blockDim.x + threadIdx.x;
    if (idx >= NN * NN) return;
    int k = idx >> 9;
    int n = idx & 511;
    int m = ((2 * n + 1) * k) & 2047;              // mod 2048 (exact int)
    float v = cospif((float)m * (1.0f / 1024.0f)) * 0.0625f;  // cospif arg exact
    if (k == 0) v *= 0.70710678118654752440f;
    g_D [k * NN + n] = v;
    g_Dt[n * NN + k] = v;
}

// ============================================================
// Pass 1: t[b,k,w,c] = sum_h D[k,h] * x[b,h,w,c]
// GEMM per b: A = D (512x512 scalar), Bmat = x[b] (512 h x 512 w, float3)
// Tile: BM=128 (k), BN=64 (w, float3), BK=8 (h). 256 threads (16x16),
// per-thread microtile 8 k x 4 w x 3 c.
// ============================================================
__global__ __launch_bounds__(256) void dct_pass1(const float* __restrict__ x) {
    __shared__ float As[8][128];        // As[h][k]
    __shared__ float Bs[8][64 * 3];     // Bs[h][w*3+c]

    const int tid = threadIdx.x;
    const int b  = blockIdx.z;
    const int k0 = blockIdx.y * 128;
    const int w0 = blockIdx.x * 64;
    const int ty = tid >> 4;            // 0..15
    const int tx = tid & 15;            // 0..15

    const float* __restrict__ xb = x + (size_t)b * NN * NN * NC;

    float acc[8][4][3];
#pragma unroll
    for (int i = 0; i < 8; i++)
#pragma unroll
        for (int j = 0; j < 4; j++)
#pragma unroll
            for (int c = 0; c < 3; c++) acc[i][j][c] = 0.0f;

    for (int h0 = 0; h0 < NN; h0 += 8) {
        // ---- load A tile: D[k0+kk][h0 .. h0+7], 128x8, transposed into As[h][k]
        {
            int kk   = tid >> 1;        // 0..127
            int part = tid & 1;         // 0..1
            float4 v = *(const float4*)&g_D[(size_t)(k0 + kk) * NN + h0 + part * 4];
            As[part * 4 + 0][kk] = v.x;
            As[part * 4 + 1][kk] = v.y;
            As[part * 4 + 2][kk] = v.z;
            As[part * 4 + 3][kk] = v.w;
        }
        // ---- load B tile: x[b][h0+h][w0..w0+63][c] : 8 rows x 192 floats = 384 float4
#pragma unroll
        for (int i = tid; i < 384; i += 256) {
            int h = i / 48;
            int f = i % 48;
            float4 v = *(const float4*)&xb[(size_t)(h0 + h) * NN * NC + (size_t)w0 * NC + f * 4];
            *(float4*)&Bs[h][f * 4] = v;
        }
        __syncthreads();

        // ---- compute
#pragma unroll
        for (int h = 0; h < 8; h++) {
            float a[8];
#pragma unroll
            for (int i = 0; i < 8; i++) a[i] = As[h][ty * 8 + i];
            float bb[12];
#pragma unroll
            for (int j = 0; j < 12; j += 4) {
                float4 v = *(const float4*)&Bs[h][tx * 12 + j];
                bb[j + 0] = v.x; bb[j + 1] = v.y; bb[j + 2] = v.z; bb[j + 3] = v.w;
            }
#pragma unroll
            for (int i = 0; i < 8; i++)
#pragma unroll
                for (int j = 0; j < 4; j++)
#pragma unroll
                    for (int c = 0; c < 3; c++)
                        acc[i][j][c] = fmaf(a[i], bb[j * 3 + c], acc[i][j][c]);
        }
        __syncthreads();
    }

    // ---- write t[b][k][w][c]: 12 contiguous floats per (thread,row) = 3 float4
#pragma unroll
    for (int i = 0; i < 8; i++) {
        int k = k0 + ty * 8 + i;
        float* dst = g_t + ((((size_t)b * NN + k) * NN) + w0 + tx * 4) * NC;
        float4 v0 = make_float4(acc[i][0][0], acc[i][0][1], acc[i][0][2], acc[i][1][0]);
        float4 v1 = make_float4(acc[i][1][1], acc[i][1][2], acc[i][2][0], acc[i][2][1]);
        float4 v2 = make_float4(acc[i][2][2], acc[i][3][0], acc[i][3][1], acc[i][3][2]);
        *(float4*)(dst + 0) = v0;
        *(float4*)(dst + 4) = v1;
        *(float4*)(dst + 8) = v2;
    }
}

// ============================================================
// Pass 2: out[b,k,l,c] = sum_w t[b,k,w,c] * Dt[w,l]
// GEMM per b: A = t[b] (512 k x 512 w, float3), Bmat = Dt (512x512 scalar)
// Tile: BM=128 (k, float3), BN=64 (l), BK=8 (w). 256 threads (16x16),
// per-thread microtile 8 k x 4 l x 3 c.
// ============================================================
__global__ __launch_bounds__(256) void dct_pass2(float* __restrict__ out) {
    __shared__ float As[8][128 * 3];    // As[w][k*3+c]
    __shared__ float Bs[8][64];         // Bs[w][l]

    const int tid = threadIdx.x;
    const int b  = blockIdx.z;
    const int k0 = blockIdx.y * 128;
    const int l0 = blockIdx.x * 64;
    const int ty = tid >> 4;
    const int tx = tid & 15;

    const float* __restrict__ tb = g_t + (size_t)b * NN * NN * NC;

    float acc[8][4][3];
#pragma unroll
    for (int i = 0; i < 8; i++)
#pragma unroll
        for (int j = 0; j < 4; j++)
#pragma unroll
            for (int c = 0; c < 3; c++) acc[i][j][c] = 0.0f;

    for (int w0 = 0; w0 < NN; w0 += 8) {
        // ---- load A tile: t[b][k0+kk][w0..w0+7][c] = 24 floats per k-row = 6 float4
#pragma unroll
        for (int i = tid; i < 128 * 6; i += 256) {
            int kk = i / 6;
            int f4 = i % 6;
            float4 v = *(const float4*)&tb[(((size_t)(k0 + kk) * NN) + w0) * NC + f4 * 4];
            int base = f4 * 4;              // float index within 24 (= w_l*3 + c)
            As[(base + 0) / 3][kk * 3 + (base + 0) % 3] = v.x;
            As[(base + 1) / 3][kk * 3 + (base + 1) % 3] = v.y;
            As[(base + 2) / 3][kk * 3 + (base + 2) % 3] = v.z;
            As[(base + 3) / 3][kk * 3 + (base + 3) % 3] = v.w;
        }
        // ---- load B tile: Dt[w0+w][l0..l0+63] : 8 rows x 16 float4 = 128 float4
        if (tid < 128) {
            int w = tid >> 4;           // 0..7
            int f = tid & 15;           // 0..15
            float4 v = *(const float4*)&g_Dt[(size_t)(w0 + w) * NN + l0 + f * 4];
            *(float4*)&Bs[w][f * 4] = v;
        }
        __syncthreads();

        // ---- compute
#pragma unroll
        for (int w = 0; w < 8; w++) {
            float a[24];
#pragma unroll
            for (int q = 0; q < 24; q += 4) {
                float4 v = *(const float4*)&As[w][ty * 24 + q];
                a[q + 0] = v.x; a[q + 1] = v.y; a[q + 2] = v.z; a[q + 3] = v.w;
            }
            float bb[4];
#pragma unroll
            for (int j = 0; j < 4; j++) bb[j] = Bs[w][tx * 4 + j];
#pragma unroll
            for (int i = 0; i < 8; i++)
#pragma unroll
                for (int j = 0; j < 4; j++)
#pragma unroll
                    for (int c = 0; c < 3; c++)
                        acc[i][j][c] = fmaf(a[i * 3 + c], bb[j], acc[i][j][c]);
        }
        __syncthreads();
    }

    // ---- write out[b][k][l][c]
#pragma unroll
    for (int i = 0; i < 8; i++) {
        int k = k0 + ty * 8 + i;
        float* dst = out + ((((size_t)b * NN + k) * NN) + l0 + tx * 4) * NC;
        float4 v0 = make_float4(acc[i][0][0], acc[i][0][1], acc[i][0][2], acc[i][1][0]);
        float4 v1 = make_float4(acc[i][1][1], acc[i][1][2], acc[i][2][0], acc[i][2][1]);
        float4 v2 = make_float4(acc[i][2][2], acc[i][3][0], acc[i][3][1], acc[i][3][2]);
        *(float4*)(dst + 0) = v0;
        *(float4*)(dst + 4) = v1;
        *(float4*)(dst + 8) = v2;
    }
}

extern "C" void kernel_launch(void* const* d_in, const int* in_sizes, int n_in,
                              void* d_out, int out_size) {
    (void)in_sizes; (void)n_in; (void)out_size;
    const float* x = (const float*)d_in[0];
    float* out = (float*)d_out;

    init_dct_kernel<<<512, 512>>>();

    dim3 grid(NN / 64, NN / 128, NB);   // (8, 4, 32)
    dct_pass1<<<grid, 256>>>(x);
    dct_pass2<<<grid, 256>>>(out);
}

// round 6
// speedup vs baseline: 1.9194x; 1.9194x over previous
#include <cuda_runtime.h>
#include <cuda_bf16.h>
#include <cstdint>
#include <math.h>

#define NB 32
#define NN 512
#define NPLANES 96
#define PLANE ((size_t)NN * NN)

// ---------------- device globals (no allocation allowed) ----------------
__device__ __align__(1024) __nv_bfloat16 g_Dh[NN * NN];            // D hi  [k][h]
__device__ __align__(1024) __nv_bfloat16 g_Dl[NN * NN];            // D lo
__device__ __align__(1024) __nv_bfloat16 g_xh[NPLANES * NN * NN];  // x^T hi [p][w][h]
__device__ __align__(1024) __nv_bfloat16 g_xl[NPLANES * NN * NN];
__device__ __align__(1024) __nv_bfloat16 g_th[NPLANES * NN * NN];  // t hi  [p][k][w]
__device__ __align__(1024) __nv_bfloat16 g_tl[NPLANES * NN * NN];

// ---------------- helpers ----------------
__device__ __forceinline__ uint32_t smem_to_u32(const void* smem_ptr) {
    uint32_t addr;
    asm("{ .reg .u64 tmp; cvta.to.shared.u64 tmp, %1; cvt.u32.u64 %0, tmp; }"
        : "=r"(addr) : "l"(smem_ptr));
    return addr;
}
#define CP_ASYNC_16(saddr, gptr) \
    asm volatile("cp.async.cg.shared.global [%0], [%1], 16;" \
        :: "r"((uint32_t)(saddr)), "l"(gptr) : "memory")
#define CP_COMMIT() asm volatile("cp.async.commit_group;" ::: "memory")
#define CP_WAIT(n)  asm volatile("cp.async.wait_group %0;" :: "n"(n) : "memory")

__device__ __forceinline__ void ldsm4(uint32_t r[4], uint32_t addr) {
    asm volatile("ldmatrix.sync.aligned.m8n8.x4.shared.b16 {%0,%1,%2,%3}, [%4];"
        : "=r"(r[0]), "=r"(r[1]), "=r"(r[2]), "=r"(r[3]) : "r"(addr));
}
__device__ __forceinline__ void mma16816(float c[4], const uint32_t a[4],
                                         uint32_t b0, uint32_t b1) {
    asm volatile(
        "mma.sync.aligned.m16n8k16.row.col.f32.bf16.bf16.f32 "
        "{%0,%1,%2,%3}, {%4,%5,%6,%7}, {%8,%9}, {%0,%1,%2,%3};"
        : "+f"(c[0]), "+f"(c[1]), "+f"(c[2]), "+f"(c[3])
        : "r"(a[0]), "r"(a[1]), "r"(a[2]), "r"(a[3]), "r"(b0), "r"(b1));
}

// ---------------- kernel 0: DCT matrix, bf16 hi/lo split ----------------
__global__ void init_dct_kernel() {
    int idx = blockIdx.x * blockDim.x + threadIdx.x;   // exactly 512*512 threads
    int k = idx >> 9;
    int n = idx & 511;
    int m = ((2 * n + 1) * k) & 2047;                  // exact mod 4N
    float v = cospif((float)m * (1.0f / 1024.0f)) * 0.0625f;
    if (k == 0) v *= 0.70710678118654752440f;
    __nv_bfloat16 hi = __float2bfloat16(v);
    g_Dh[idx] = hi;
    g_Dl[idx] = __float2bfloat16(v - __bfloat162float(hi));
}

// ------- kernel 1: de-interleave + transpose + bf16 split of x -------
// x[b][h][w][c] fp32  ->  g_xh/g_xl [p=b*3+c][w][h] bf16
__global__ __launch_bounds__(256) void split_transpose_kernel(const float* __restrict__ x) {
    __shared__ float tsm[3][32][33];
    const int tid = threadIdx.x;
    const int b = blockIdx.z, h0 = blockIdx.y * 32, w0 = blockIdx.x * 32;
    const float* base = x + (((size_t)b * NN + h0) * NN + w0) * 3;

    for (int i = tid; i < 768; i += 256) {             // 32 rows x 24 float4
        int row = i / 24, f4 = i % 24;
        float4 v = *(const float4*)(base + (size_t)row * NN * 3 + f4 * 4);
        int f = f4 * 4;
        tsm[(f + 0) % 3][(f + 0) / 3][row] = v.x;
        tsm[(f + 1) % 3][(f + 1) / 3][row] = v.y;
        tsm[(f + 2) % 3][(f + 2) / 3][row] = v.z;
        tsm[(f + 3) % 3][(f + 3) / 3][row] = v.w;
    }
    __syncthreads();

    const int wl = tid >> 3;
    const int hs = (tid & 7) * 4;
#pragma unroll
    for (int c = 0; c < 3; c++) {
        size_t p = (size_t)(b * 3 + c);
        size_t dst = (p * NN + (w0 + wl)) * NN + h0 + hs;
        union { __nv_bfloat16 h[4]; uint2 u; } uh, ul;
#pragma unroll
        for (int j = 0; j < 4; j++) {
            float f = tsm[c][wl][hs + j];
            __nv_bfloat16 hi = __float2bfloat16(f);
            uh.h[j] = hi;
            ul.h[j] = __float2bfloat16(f - __bfloat162float(hi));
        }
        *(uint2*)&g_xh[dst] = uh.u;
        *(uint2*)&g_xl[dst] = ul.u;
    }
}

// ---------------- HMMA GEMM: 128x128 tile, K=512, 3xBF16 split ----------------
// pass1: A=D[k][h], B=xT[w][h]  -> t[k][w]  (bf16 hi/lo out)
// pass2: A=t[k][w], B=D[l][w]   -> out[b][k][l][c] (fp32, interleaved)
// smem: 2 stages x (Ah|Al|Bh|Bl), each matrix 128 rows x 64 bf16 (128B, SW128)
#define MAT_BYTES   16384
#define STAGE_BYTES 65536
#define GEMM_SMEM_TOTAL (2 * STAGE_BYTES)

__global__ __launch_bounds__(256, 1)
void gemm_hmma_kernel(float* __restrict__ Out, int pass) {
    extern __shared__ char smem[];
    const uint32_t smem_base = smem_to_u32(smem);
    const int tid  = threadIdx.x;
    const int wid  = tid >> 5;
    const int lane = tid & 31;
    const int p  = blockIdx.z;
    const int m0 = blockIdx.y * 128;
    const int n0 = blockIdx.x * 128;

    const __nv_bfloat16 *gah, *gal, *gbh, *gbl;
    if (pass == 1) {
        gah = g_Dh;                      gal = g_Dl;
        gbh = g_xh + (size_t)p * PLANE;  gbl = g_xl + (size_t)p * PLANE;
    } else {
        gah = g_th + (size_t)p * PLANE;  gal = g_tl + (size_t)p * PLANE;
        gbh = g_Dh;                      gbl = g_Dl;
    }
    gah += (size_t)m0 * NN;  gal += (size_t)m0 * NN;
    gbh += (size_t)n0 * NN;  gbl += (size_t)n0 * NN;

    // warp tiling: 4 warps along M (32 rows each), 2 along N (64 cols each)
    const int wm = wid & 3;
    const int wn = wid >> 2;

    float acc[2][8][4];
#pragma unroll
    for (int t = 0; t < 2; t++)
#pragma unroll
        for (int nt = 0; nt < 8; nt++)
#pragma unroll
            for (int r = 0; r < 4; r++) acc[t][nt][r] = 0.0f;

    // ---- async copy of one K-chunk (64 k) into stage s ----
    auto copy_chunk = [&](int ch, int s) {
        const int k0c = ch * 64;
        const uint32_t sb = smem_base + s * STAGE_BYTES;
#pragma unroll
        for (int i = tid; i < 4096; i += 256) {
            int mat = i >> 10;
            int r   = (i >> 3) & 127;
            int c16 = i & 7;
            const __nv_bfloat16* src =
                (mat == 0) ? gah : (mat == 1) ? gal : (mat == 2) ? gbh : gbl;
            uint32_t off = (uint32_t)(r * 128 + c16 * 16);
            uint32_t sw  = off ^ ((off >> 3) & 0x70);
            CP_ASYNC_16(sb + mat * MAT_BYTES + sw, src + (size_t)r * NN + k0c + c16 * 8);
        }
    };

    // ldmatrix per-lane geometry (SW128: xor low-3 row bits into 16B column)
    const int arow  = wm * 32 + (lane & 15);            // + t*16
    const uint32_t acoff = (uint32_t)((lane >> 4) * 16);
    const uint32_t axor  = (uint32_t)((arow & 7) << 4);
    const int brow  = wn * 64 + (lane & 7) + ((lane >> 4) << 3);  // + q*16
    const uint32_t bcoff = (uint32_t)(((lane >> 3) & 1) * 16);
    const uint32_t bxor  = (uint32_t)((brow & 7) << 4);

    copy_chunk(0, 0);
    CP_COMMIT();

    for (int ch = 0; ch < 8; ch++) {
        const int s = ch & 1;
        if (ch < 7) {
            copy_chunk(ch + 1, s ^ 1);
            CP_COMMIT();
            CP_WAIT(1);
        } else {
            CP_WAIT(0);
        }
        __syncthreads();

        const uint32_t sb = smem_base + s * STAGE_BYTES;
#pragma unroll
        for (int j = 0; j < 4; j++) {
            uint32_t ah[2][4], al[2][4], bh[4][4], bl[4][4];
#pragma unroll
            for (int t = 0; t < 2; t++) {
                uint32_t rb = (uint32_t)((arow + t * 16) * 128);
                uint32_t cc = ((uint32_t)(j * 32) | acoff) ^ axor;
                ldsm4(ah[t], sb + 0 * MAT_BYTES + rb + cc);
                ldsm4(al[t], sb + 1 * MAT_BYTES + rb + cc);
            }
#pragma unroll
            for (int q = 0; q < 4; q++) {
                uint32_t rb = (uint32_t)((brow + q * 16) * 128);
                uint32_t cc = ((uint32_t)(j * 32) | bcoff) ^ bxor;
                ldsm4(bh[q], sb + 2 * MAT_BYTES + rb + cc);
                ldsm4(bl[q], sb + 3 * MAT_BYTES + rb + cc);
            }
#pragma unroll
            for (int t = 0; t < 2; t++)
#pragma unroll
                for (int q = 0; q < 4; q++)
#pragma unroll
                    for (int h = 0; h < 2; h++) {
                        int nt = q * 2 + h;
                        mma16816(acc[t][nt], ah[t], bh[q][h * 2], bh[q][h * 2 + 1]); // hi*hi
                        mma16816(acc[t][nt], ah[t], bl[q][h * 2], bl[q][h * 2 + 1]); // hi*lo
                        mma16816(acc[t][nt], al[t], bh[q][h * 2], bh[q][h * 2 + 1]); // lo*hi
                    }
        }
        __syncthreads();   // protect stage before it is refilled
    }

    // ---- epilogue: fragments -> padded smem -> coalesced global ----
    const int er = lane >> 2;
    const int ec = (lane & 3) * 2;

    if (pass == 1) {
        // hi/lo bf16 buffers, row stride 144 bf16 (288B: 16B-aligned rows)
        __nv_bfloat16* eh = (__nv_bfloat16*)smem;
        __nv_bfloat16* el = (__nv_bfloat16*)(smem + 36864);
#pragma unroll
        for (int t = 0; t < 2; t++)
#pragma unroll
            for (int nt = 0; nt < 8; nt++) {
                int row = wm * 32 + t * 16 + er;
                int col = wn * 64 + nt * 8 + ec;
#pragma unroll
                for (int hlf = 0; hlf < 2; hlf++) {  // rows er and er+8
                    float f0 = acc[t][nt][hlf * 2 + 0];
                    float f1 = acc[t][nt][hlf * 2 + 1];
                    __nv_bfloat16 h0 = __float2bfloat16(f0);
                    __nv_bfloat16 h1 = __float2bfloat16(f1);
                    __nv_bfloat16 l0 = __float2bfloat16(f0 - __bfloat162float(h0));
                    __nv_bfloat16 l1 = __float2bfloat16(f1 - __bfloat162float(h1));
                    int o = (row + hlf * 8) * 144 + col;
                    union { __nv_bfloat16 h[2]; uint32_t u; } ph, pl;
                    ph.h[0] = h0; ph.h[1] = h1;
                    pl.h[0] = l0; pl.h[1] = l1;
                    *(uint32_t*)&eh[o] = ph.u;
                    *(uint32_t*)&el[o] = pl.u;
                }
            }
        __syncthreads();
        const int r = tid >> 1, half = tid & 1;
        __nv_bfloat16* dh = g_th + ((size_t)p * NN + m0 + r) * NN + n0 + half * 64;
        __nv_bfloat16* dl = g_tl + ((size_t)p * NN + m0 + r) * NN + n0 + half * 64;
#pragma unroll
        for (int j = 0; j < 8; j++) {
            *(uint4*)(dh + j * 8) = *(const uint4*)(eh + r * 144 + half * 64 + j * 8);
            *(uint4*)(dl + j * 8) = *(const uint4*)(el + r * 144 + half * 64 + j * 8);
        }
    } else {
        // fp32 buffer, row stride 132 floats (528B: 16B-aligned, bank-shifted)
        float* ef = (float*)smem;
#pragma unroll
        for (int t = 0; t < 2; t++)
#pragma unroll
            for (int nt = 0; nt < 8; nt++) {
                int row = wm * 32 + t * 16 + er;
                int col = wn * 64 + nt * 8 + ec;
#pragma unroll
                for (int hlf = 0; hlf < 2; hlf++) {
                    int o = (row + hlf * 8) * 132 + col;
                    *(float2*)&ef[o] =
                        make_float2(acc[t][nt][hlf * 2 + 0], acc[t][nt][hlf * 2 + 1]);
                }
            }
        __syncthreads();
        const int r = tid >> 1, half = tid & 1;
        const int b = p / 3, c = p % 3;
        float* dst = Out + (((size_t)b * NN + m0 + r) * NN + n0 + half * 64) * 3 + c;
#pragma unroll 8
        for (int j = 0; j < 64; j++)
            dst[j * 3] = ef[r * 132 + half * 64 + j];
    }
}

// ---------------- launcher ----------------
extern "C" void kernel_launch(void* const* d_in, const int* in_sizes, int n_in,
                              void* d_out, int out_size) {
    (void)in_sizes; (void)n_in; (void)out_size;
    const float* x = (const float*)d_in[0];
    float* out = (float*)d_out;

    cudaFuncSetAttribute(gemm_hmma_kernel,
                         cudaFuncAttributeMaxDynamicSharedMemorySize, GEMM_SMEM_TOTAL);

    init_dct_kernel<<<512, 512>>>();
    split_transpose_kernel<<<dim3(16, 16, NB), 256>>>(x);

    dim3 grid(4, 4, NPLANES);
    gemm_hmma_kernel<<<grid, 256, GEMM_SMEM_TOTAL>>>(nullptr, 1);
    gemm_hmma_kernel<<<grid, 256, GEMM_SMEM_TOTAL>>>(out, 2);
}

// round 8
// speedup vs baseline: 1.9456x; 1.0137x over previous
#include <cuda_runtime.h>
#include <cuda_bf16.h>
#include <cstdint>
#include <math.h>

#define NB 32
#define NN 512
#define NPLANES 96
#define PLANE ((size_t)NN * NN)

// ---------------- device globals (no allocation allowed) ----------------
__device__ __align__(1024) __nv_bfloat16 g_Dh[NN * NN];            // D hi  [k][h]
__device__ __align__(1024) __nv_bfloat16 g_Dl[NN * NN];            // D lo
__device__ __align__(1024) __nv_bfloat16 g_xh[NPLANES * NN * NN];  // x^T hi [p][w][h]
__device__ __align__(1024) __nv_bfloat16 g_xl[NPLANES * NN * NN];
__device__ __align__(1024) __nv_bfloat16 g_th[NPLANES * NN * NN];  // t hi  [p][k][w]
__device__ __align__(1024) __nv_bfloat16 g_tl[NPLANES * NN * NN];

// ---------------- helpers ----------------
__device__ __forceinline__ uint32_t smem_to_u32(const void* smem_ptr) {
    uint32_t addr;
    asm("{ .reg .u64 tmp; cvta.to.shared.u64 tmp, %1; cvt.u32.u64 %0, tmp; }"
        : "=r"(addr) : "l"(smem_ptr));
    return addr;
}
#define CP_ASYNC_16(saddr, gptr) \
    asm volatile("cp.async.cg.shared.global [%0], [%1], 16;" \
        :: "r"((uint32_t)(saddr)), "l"(gptr) : "memory")
#define CP_COMMIT() asm volatile("cp.async.commit_group;" ::: "memory")
#define CP_WAIT(n)  asm volatile("cp.async.wait_group %0;" :: "n"(n) : "memory")

__device__ __forceinline__ void ldsm4(uint32_t r[4], uint32_t addr) {
    asm volatile("ldmatrix.sync.aligned.m8n8.x4.shared.b16 {%0,%1,%2,%3}, [%4];"
        : "=r"(r[0]), "=r"(r[1]), "=r"(r[2]), "=r"(r[3]) : "r"(addr));
}
__device__ __forceinline__ void mma16816(float c[4], const uint32_t a[4],
                                         uint32_t b0, uint32_t b1) {
    asm volatile(
        "mma.sync.aligned.m16n8k16.row.col.f32.bf16.bf16.f32 "
        "{%0,%1,%2,%3}, {%4,%5,%6,%7}, {%8,%9}, {%0,%1,%2,%3};"
        : "+f"(c[0]), "+f"(c[1]), "+f"(c[2]), "+f"(c[3])
        : "r"(a[0]), "r"(a[1]), "r"(a[2]), "r"(a[3]), "r"(b0), "r"(b1));
}

// ---------------- kernel 0: DCT matrix, bf16 hi/lo split ----------------
__global__ void init_dct_kernel() {
    int idx = blockIdx.x * blockDim.x + threadIdx.x;   // exactly 512*512 threads
    int k = idx >> 9;
    int n = idx & 511;
    int m = ((2 * n + 1) * k) & 2047;                  // exact mod 4N
    float v = cospif((float)m * (1.0f / 1024.0f)) * 0.0625f;
    if (k == 0) v *= 0.70710678118654752440f;
    __nv_bfloat16 hi = __float2bfloat16(v);
    g_Dh[idx] = hi;
    g_Dl[idx] = __float2bfloat16(v - __bfloat162float(hi));
}

// ------- kernel 1: de-interleave + transpose + bf16 split of x -------
// x[b][h][w][c] fp32  ->  g_xh/g_xl [p=b*3+c][w][h] bf16
__global__ __launch_bounds__(256) void split_transpose_kernel(const float* __restrict__ x) {
    __shared__ float tsm[3][32][33];
    const int tid = threadIdx.x;
    const int b = blockIdx.z, h0 = blockIdx.y * 32, w0 = blockIdx.x * 32;
    const float* base = x + (((size_t)b * NN + h0) * NN + w0) * 3;

    for (int i = tid; i < 768; i += 256) {             // 32 rows x 24 float4
        int row = i / 24, f4 = i % 24;
        float4 v = *(const float4*)(base + (size_t)row * NN * 3 + f4 * 4);
        int f = f4 * 4;
        tsm[(f + 0) % 3][(f + 0) / 3][row] = v.x;
        tsm[(f + 1) % 3][(f + 1) / 3][row] = v.y;
        tsm[(f + 2) % 3][(f + 2) / 3][row] = v.z;
        tsm[(f + 3) % 3][(f + 3) / 3][row] = v.w;
    }
    __syncthreads();

    const int wl = tid >> 3;
    const int hs = (tid & 7) * 4;
#pragma unroll
    for (int c = 0; c < 3; c++) {
        size_t p = (size_t)(b * 3 + c);
        size_t dst = (p * NN + (w0 + wl)) * NN + h0 + hs;
        union { __nv_bfloat16 h[4]; uint2 u; } uh, ul;
#pragma unroll
        for (int j = 0; j < 4; j++) {
            float f = tsm[c][wl][hs + j];
            __nv_bfloat16 hi = __float2bfloat16(f);
            uh.h[j] = hi;
            ul.h[j] = __float2bfloat16(f - __bfloat162float(hi));
        }
        *(uint2*)&g_xh[dst] = uh.u;
        *(uint2*)&g_xl[dst] = ul.u;
    }
}

// ---------------- HMMA GEMM: 128x128 tile, K=512, 3xBF16 split ----------------
// pass1: A=D[k][h], B=xT[w][h]  -> t[k][w]  (bf16 hi/lo out)
// pass2: A=t[k][w], B=D[l][w]   -> out[b][k][l][c] (fp32, interleaved)
// smem: 3 stages x (Ah|Al|Bh|Bl), each matrix 128 rows x 32 bf16 (64B, SW64)
// 2 CTAs / SM (96KB smem each, <=128 regs)
#define MAT_BYTES   8192
#define STAGE_BYTES 32768
#define NSTAGE      3
#define NCHUNK      16
#define GEMM_SMEM_TOTAL (NSTAGE * STAGE_BYTES)

__global__ __launch_bounds__(256, 2)
void gemm_hmma_kernel(float* __restrict__ Out, int pass) {
    extern __shared__ char smem[];
    const uint32_t smem_base = smem_to_u32(smem);
    const int tid  = threadIdx.x;
    const int wid  = tid >> 5;
    const int lane = tid & 31;
    const int p  = blockIdx.z;
    const int m0 = blockIdx.y * 128;
    const int n0 = blockIdx.x * 128;

    const __nv_bfloat16 *gah, *gal, *gbh, *gbl;
    if (pass == 1) {
        gah = g_Dh;                      gal = g_Dl;
        gbh = g_xh + (size_t)p * PLANE;  gbl = g_xl + (size_t)p * PLANE;
    } else {
        gah = g_th + (size_t)p * PLANE;  gal = g_tl + (size_t)p * PLANE;
        gbh = g_Dh;                      gbl = g_Dl;
    }
    gah += (size_t)m0 * NN;  gal += (size_t)m0 * NN;
    gbh += (size_t)n0 * NN;  gbl += (size_t)n0 * NN;

    // warp tiling: 4 warps along M (32 rows each), 2 along N (64 cols each)
    const int wm = wid & 3;
    const int wn = wid >> 2;

    float acc[2][8][4];
#pragma unroll
    for (int t = 0; t < 2; t++)
#pragma unroll
        for (int nt = 0; nt < 8; nt++)
#pragma unroll
            for (int r = 0; r < 4; r++) acc[t][nt][r] = 0.0f;

    // ---- async copy of one K-chunk (32 k) into stage s ----
    auto copy_chunk = [&](int ch, int s) {
        const int k0c = ch * 32;
        const uint32_t sb = smem_base + s * STAGE_BYTES;
#pragma unroll
        for (int i = tid; i < 2048; i += 256) {
            int mat = i >> 9;          // 0..3
            int seg = i & 511;         // 128 rows x 4 16B segments
            int r   = seg >> 2;
            int c16 = seg & 3;
            const __nv_bfloat16* src =
                (mat == 0) ? gah : (mat == 1) ? gal : (mat == 2) ? gbh : gbl;
            uint32_t off = (uint32_t)(r * 64 + c16 * 16);
            uint32_t sw  = off ^ ((off >> 3) & 0x30);   // SW64
            CP_ASYNC_16(sb + mat * MAT_BYTES + sw, src + (size_t)r * NN + k0c + c16 * 8);
        }
    };

    // ldmatrix per-lane geometry (SW64 rows of 64B)
    const int arow = wm * 32 + (lane & 15);                        // + t*16
    const int acol = lane >> 4;                                    // + j*2
    const int brow = wn * 64 + (lane & 7) + ((lane >> 4) << 3);    // + q*16
    const int bcol = (lane >> 3) & 1;                              // + j*2

    copy_chunk(0, 0); CP_COMMIT();
    copy_chunk(1, 1); CP_COMMIT();

    for (int ch = 0; ch < NCHUNK; ch++) {
        const int s = ch % NSTAGE;
        CP_WAIT(1);                       // chunk ch resident
        __syncthreads();
        if (ch + 2 < NCHUNK) {            // prefetch into slot consumed at ch-1
            copy_chunk(ch + 2, (ch + 2) % NSTAGE);
            CP_COMMIT();
        }

        const uint32_t sb = smem_base + s * STAGE_BYTES;
#pragma unroll
        for (int j = 0; j < 2; j++) {
            uint32_t ah[2][4], al[2][4];
#pragma unroll
            for (int t = 0; t < 2; t++) {
                uint32_t off = (uint32_t)((arow + t * 16) * 64 + (acol + j * 2) * 16);
                uint32_t sw  = off ^ ((off >> 3) & 0x30);
                ldsm4(ah[t], sb + 0 * MAT_BYTES + sw);
                ldsm4(al[t], sb + 1 * MAT_BYTES + sw);
            }
#pragma unroll
            for (int q = 0; q < 4; q++) {
                uint32_t bh[4], bl[4];
                uint32_t off = (uint32_t)((brow + q * 16) * 64 + (bcol + j * 2) * 16);
                uint32_t sw  = off ^ ((off >> 3) & 0x30);
                ldsm4(bh, sb + 2 * MAT_BYTES + sw);
                ldsm4(bl, sb + 3 * MAT_BYTES + sw);
#pragma unroll
                for (int t = 0; t < 2; t++)
#pragma unroll
                    for (int h = 0; h < 2; h++) {
                        int nt = q * 2 + h;
                        mma16816(acc[t][nt], ah[t], bh[h * 2], bh[h * 2 + 1]); // hi*hi
                        mma16816(acc[t][nt], ah[t], bl[h * 2], bl[h * 2 + 1]); // hi*lo
                        mma16816(acc[t][nt], al[t], bh[h * 2], bh[h * 2 + 1]); // lo*hi
                    }
            }
        }
    }
    __syncthreads();   // all compute done before smem reuse by epilogue

    // ---- epilogue: fragments -> padded smem -> coalesced global ----
    const int er = lane >> 2;
    const int ec = (lane & 3) * 2;

    if (pass == 1) {
        // hi/lo bf16 buffers, row stride 144 bf16 (288B: 16B-aligned rows)
        __nv_bfloat16* eh = (__nv_bfloat16*)smem;
        __nv_bfloat16* el = (__nv_bfloat16*)(smem + 36864);
#pragma unroll
        for (int t = 0; t < 2; t++)
#pragma unroll
            for (int nt = 0; nt < 8; nt++) {
                int row = wm * 32 + t * 16 + er;
                int col = wn * 64 + nt * 8 + ec;
#pragma unroll
                for (int hlf = 0; hlf < 2; hlf++) {  // rows er and er+8
                    float f0 = acc[t][nt][hlf * 2 + 0];
                    float f1 = acc[t][nt][hlf * 2 + 1];
                    __nv_bfloat16 h0 = __float2bfloat16(f0);
                    __nv_bfloat16 h1 = __float2bfloat16(f1);
                    __nv_bfloat16 l0 = __float2bfloat16(f0 - __bfloat162float(h0));
                    __nv_bfloat16 l1 = __float2bfloat16(f1 - __bfloat162float(h1));
                    int o = (row + hlf * 8) * 144 + col;
                    union { __nv_bfloat16 h[2]; uint32_t u; } ph, pl;
                    ph.h[0] = h0; ph.h[1] = h1;
                    pl.h[0] = l0; pl.h[1] = l1;
                    *(uint32_t*)&eh[o] = ph.u;
                    *(uint32_t*)&el[o] = pl.u;
                }
            }
        __syncthreads();
        const int r = tid >> 1, half = tid & 1;
        __nv_bfloat16* dh = g_th + ((size_t)p * NN + m0 + r) * NN + n0 + half * 64;
        __nv_bfloat16* dl = g_tl + ((size_t)p * NN + m0 + r) * NN + n0 + half * 64;
#pragma unroll
        for (int j = 0; j < 8; j++) {
            *(uint4*)(dh + j * 8) = *(const uint4*)(eh + r * 144 + half * 64 + j * 8);
            *(uint4*)(dl + j * 8) = *(const uint4*)(el + r * 144 + half * 64 + j * 8);
        }
    } else {
        // fp32 buffer, row stride 132 floats (528B: 16B-aligned, bank-shifted)
        float* ef = (float*)smem;
#pragma unroll
        for (int t = 0; t < 2; t++)
#pragma unroll
            for (int nt = 0; nt < 8; nt++) {
                int row = wm * 32 + t * 16 + er;
                int col = wn * 64 + nt * 8 + ec;
#pragma unroll
                for (int hlf = 0; hlf < 2; hlf++) {
                    int o = (row + hlf * 8) * 132 + col;
                    *(float2*)&ef[o] =
                        make_float2(acc[t][nt][hlf * 2 + 0], acc[t][nt][hlf * 2 + 1]);
                }
            }
        __syncthreads();
        const int r = tid >> 1, half = tid & 1;
        const int b = p / 3, c = p % 3;
        float* dst = Out + (((size_t)b * NN + m0 + r) * NN + n0 + half * 64) * 3 + c;
#pragma unroll 8
        for (int j = 0; j < 64; j++)
            dst[j * 3] = ef[r * 132 + half * 64 + j];
    }
}

// ---------------- launcher ----------------
extern "C" void kernel_launch(void* const* d_in, const int* in_sizes, int n_in,
                              void* d_out, int out_size) {
    (void)in_sizes; (void)n_in; (void)out_size;
    const float* x = (const float*)d_in[0];
    float* out = (float*)d_out;

    cudaFuncSetAttribute(gemm_hmma_kernel,
                         cudaFuncAttributeMaxDynamicSharedMemorySize, GEMM_SMEM_TOTAL);

    init_dct_kernel<<<512, 512>>>();
    split_transpose_kernel<<<dim3(16, 16, NB), 256>>>(x);

    dim3 grid(4, 4, NPLANES);
    gemm_hmma_kernel<<<grid, 256, GEMM_SMEM_TOTAL>>>(nullptr, 1);
    gemm_hmma_kernel<<<grid, 256, GEMM_SMEM_TOTAL>>>(out, 2);
}

// round 9
// speedup vs baseline: 2.4078x; 1.2376x over previous
#include <cuda_runtime.h>
#include <cuda_bf16.h>
#include <cstdint>
#include <math.h>

#define NB 32
#define NN 512
#define NH 256
#define NPLANES 96
#define HALF ((size_t)NN * NH)   // 512*256

// ---------------- device globals (no allocation allowed) ----------------
__device__ __align__(1024) __nv_bfloat16 g_De_h[NH * NH], g_De_l[NH * NH]; // De[r][h]
__device__ __align__(1024) __nv_bfloat16 g_Do_h[NH * NH], g_Do_l[NH * NH]; // Do[r][h]
__device__ __align__(1024) __nv_bfloat16 g_xe_h[NPLANES * HALF], g_xe_l[NPLANES * HALF]; // [p][w][h']
__device__ __align__(1024) __nv_bfloat16 g_xo_h[NPLANES * HALF], g_xo_l[NPLANES * HALF];
__device__ __align__(1024) float         g_t[NPLANES * (size_t)NN * NN];   // t_perm fp32 [p][k'][w]
__device__ __align__(1024) __nv_bfloat16 g_te_h[NPLANES * HALF], g_te_l[NPLANES * HALF]; // [p][k'][w']
__device__ __align__(1024) __nv_bfloat16 g_to_h[NPLANES * HALF], g_to_l[NPLANES * HALF];

// ---------------- helpers ----------------
__device__ __forceinline__ uint32_t smem_to_u32(const void* smem_ptr) {
    uint32_t addr;
    asm("{ .reg .u64 tmp; cvta.to.shared.u64 tmp, %1; cvt.u32.u64 %0, tmp; }"
        : "=r"(addr) : "l"(smem_ptr));
    return addr;
}
#define CP_ASYNC_16(saddr, gptr) \
    asm volatile("cp.async.cg.shared.global [%0], [%1], 16;" \
        :: "r"((uint32_t)(saddr)), "l"(gptr) : "memory")
#define CP_COMMIT() asm volatile("cp.async.commit_group;" ::: "memory")
#define CP_WAIT(n)  asm volatile("cp.async.wait_group %0;" :: "n"(n) : "memory")

__device__ __forceinline__ void ldsm4(uint32_t r[4], uint32_t addr) {
    asm volatile("ldmatrix.sync.aligned.m8n8.x4.shared.b16 {%0,%1,%2,%3}, [%4];"
        : "=r"(r[0]), "=r"(r[1]), "=r"(r[2]), "=r"(r[3]) : "r"(addr));
}
__device__ __forceinline__ void mma16816(float c[4], const uint32_t a[4],
                                         uint32_t b0, uint32_t b1) {
    asm volatile(
        "mma.sync.aligned.m16n8k16.row.col.f32.bf16.bf16.f32 "
        "{%0,%1,%2,%3}, {%4,%5,%6,%7}, {%8,%9}, {%0,%1,%2,%3};"
        : "+f"(c[0]), "+f"(c[1]), "+f"(c[2]), "+f"(c[3])
        : "r"(a[0]), "r"(a[1]), "r"(a[2]), "r"(a[3]), "r"(b0), "r"(b1));
}
__device__ __forceinline__ void bf16split(float f, __nv_bfloat16& h, __nv_bfloat16& l) {
    h = __float2bfloat16(f);
    l = __float2bfloat16(f - __bfloat162float(h));
}

// -------- kernel 0: half-size DCT matrices De (even k) / Do (odd k), hi/lo --------
// D[k,n] = cospi(((2n+1)k mod 2048)/1024)/16; row k=0 *= 1/sqrt(2).
__global__ void init_dct_half() {
    int idx = blockIdx.x * blockDim.x + threadIdx.x;   // 256*256 threads
    int r = idx >> 8;
    int h = idx & 255;
    int me = ((2 * h + 1) * (2 * r)) & 2047;
    float ve = cospif((float)me * (1.0f / 1024.0f)) * 0.0625f;
    if (r == 0) ve *= 0.70710678118654752440f;
    bf16split(ve, g_De_h[idx], g_De_l[idx]);
    int mo = ((2 * h + 1) * (2 * r + 1)) & 2047;
    float vo = cospif((float)mo * (1.0f / 1024.0f)) * 0.0625f;
    bf16split(vo, g_Do_h[idx], g_Do_l[idx]);
}

// -------- kernel 1: de-interleave + transpose + h-fold + bf16 split of x --------
// x[b][h][w][c] fp32 -> xe/xo hi/lo [p=3b+c][w][h'<256]
__global__ __launch_bounds__(256) void fold_split_x(const float* __restrict__ x) {
    __shared__ float tA[3][32][33];
    __shared__ float tB[3][32][33];
    const int tid = threadIdx.x;
    const int b = blockIdx.z, h0 = blockIdx.y * 32, w0 = blockIdx.x * 32;
    const float* baseA = x + (((size_t)b * NN + h0) * NN + w0) * 3;
    const float* baseB = x + (((size_t)b * NN + (480 - h0)) * NN + w0) * 3;

    for (int i = tid; i < 768; i += 256) {             // 32 rows x 24 float4
        int row = i / 24, f4 = i % 24;
        float4 va = *(const float4*)(baseA + (size_t)row * NN * 3 + f4 * 4);
        float4 vb = *(const float4*)(baseB + (size_t)row * NN * 3 + f4 * 4);
        int f = f4 * 4;
        tA[(f + 0) % 3][(f + 0) / 3][row] = va.x;
        tA[(f + 1) % 3][(f + 1) / 3][row] = va.y;
        tA[(f + 2) % 3][(f + 2) / 3][row] = va.z;
        tA[(f + 3) % 3][(f + 3) / 3][row] = va.w;
        tB[(f + 0) % 3][(f + 0) / 3][row] = vb.x;
        tB[(f + 1) % 3][(f + 1) / 3][row] = vb.y;
        tB[(f + 2) % 3][(f + 2) / 3][row] = vb.z;
        tB[(f + 3) % 3][(f + 3) / 3][row] = vb.w;
    }
    __syncthreads();

    const int wl = tid >> 3;
    const int hs = (tid & 7) * 4;
#pragma unroll
    for (int c = 0; c < 3; c++) {
        size_t p = (size_t)(b * 3 + c);
        size_t dst = (p * NN + (w0 + wl)) * NH + h0 + hs;
        union { __nv_bfloat16 v[4]; uint2 u; } eh, el, oh, ol;
#pragma unroll
        for (int j = 0; j < 4; j++) {
            int hr = hs + j;
            float a = tA[c][wl][hr];
            float m = tB[c][wl][31 - hr];     // x[511-(h0+hr)]
            bf16split(a + m, eh.v[j], el.v[j]);
            bf16split(a - m, oh.v[j], ol.v[j]);
        }
        *(uint2*)&g_xe_h[dst] = eh.u;
        *(uint2*)&g_xe_l[dst] = el.u;
        *(uint2*)&g_xo_h[dst] = oh.u;
        *(uint2*)&g_xo_l[dst] = ol.u;
    }
}

// -------- kernel 3: w-fold + bf16 split of intermediate t --------
// g_t[p][k'][w] fp32 -> te/to hi/lo [p][k'][w'<256]
__global__ __launch_bounds__(256) void fold_split_t() {
    int idx = blockIdx.x * 256 + threadIdx.x;   // 96*512*64 items
    int row = idx >> 6;                          // p*512 + k'
    int q = idx & 63;
    const float* src = g_t + (size_t)row * NN;
    float4 f = *(const float4*)(src + 4 * q);
    float4 g = *(const float4*)(src + 508 - 4 * q);
    float mv[4] = {g.w, g.z, g.y, g.x};
    float fv[4] = {f.x, f.y, f.z, f.w};
    union { __nv_bfloat16 v[4]; uint2 u; } eh, el, oh, ol;
#pragma unroll
    for (int j = 0; j < 4; j++) {
        bf16split(fv[j] + mv[j], eh.v[j], el.v[j]);
        bf16split(fv[j] - mv[j], oh.v[j], ol.v[j]);
    }
    size_t dst = (size_t)row * NH + 4 * q;
    *(uint2*)&g_te_h[dst] = eh.u;
    *(uint2*)&g_te_l[dst] = el.u;
    *(uint2*)&g_to_h[dst] = oh.u;
    *(uint2*)&g_to_l[dst] = ol.u;
}

// ---------------- HMMA GEMM, K=256, 3xBF16 split, folded DCT ----------------
// pass1: per (plane, parity): t_perm[k'][w] = De/Do @ xe/xo   (fp32 out, coalesced)
// pass2: out[b][k][l][c], CTA mixes both parities (wn=0 even l, wn=1 odd l)
// smem/stage: slots 0..5 = A_h, A_l, Ao_h, Ao_l, B_h, B_l (128 rows x 64B, SW64)
#define MAT_BYTES   8192
#define STAGE_BYTES 49152
#define NSTAGE      2
#define NCHUNK      8
#define GEMM_SMEM_TOTAL (NSTAGE * STAGE_BYTES)   // 96 KB -> 2 CTAs/SM

__global__ __launch_bounds__(256, 2)
void gemm_hmma_kernel(float* __restrict__ Out, int pass) {
    extern __shared__ char smem[];
    const uint32_t smem_base = smem_to_u32(smem);
    const int tid  = threadIdx.x;
    const int wid  = tid >> 5;
    const int lane = tid & 31;
    const int p  = blockIdx.z;

    // matrix source pointers (row stride NH=256 everywhere)
    const __nv_bfloat16 *pM0, *pM1, *pM2, *pM3, *pBh0, *pBh1, *pBl0, *pBl1;
    int m0, n0, parity = 0;
    if (pass == 1) {
        parity = blockIdx.y >> 1;
        const int mt = blockIdx.y & 1;
        m0 = mt * 128;
        n0 = blockIdx.x * 128;
        pM0 = (parity ? g_Do_h : g_De_h) + (size_t)m0 * NH;
        pM1 = (parity ? g_Do_l : g_De_l) + (size_t)m0 * NH;
        pM2 = pM0; pM3 = pM1;
        pBh0 = (parity ? g_xo_h : g_xe_h) + (size_t)p * HALF + (size_t)n0 * NH;
        pBl0 = (parity ? g_xo_l : g_xe_l) + (size_t)p * HALF + (size_t)n0 * NH;
        pBh1 = pBh0; pBl1 = pBl0;
    } else {
        m0 = blockIdx.y * 128;                  // k' tile
        n0 = blockIdx.x * 64;                   // l'' offset (final l tile = 2*n0)
        pM0 = g_te_h + (size_t)p * HALF + (size_t)m0 * NH;
        pM1 = g_te_l + (size_t)p * HALF + (size_t)m0 * NH;
        pM2 = g_to_h + (size_t)p * HALF + (size_t)m0 * NH;
        pM3 = g_to_l + (size_t)p * HALF + (size_t)m0 * NH;
        pBh0 = g_De_h + (size_t)n0 * NH;        // rows 0..63
        pBl0 = g_De_l + (size_t)n0 * NH;
        pBh1 = g_Do_h + ((size_t)n0 - 64) * NH; // rows 64..127 -> Do[n0 + r-64]
        pBl1 = g_Do_l + ((size_t)n0 - 64) * NH;
    }

    const int wm = wid & 3;
    const int wn = wid >> 2;

    float acc[2][8][4];
#pragma unroll
    for (int t = 0; t < 2; t++)
#pragma unroll
        for (int nt = 0; nt < 8; nt++)
#pragma unroll
            for (int r = 0; r < 4; r++) acc[t][nt][r] = 0.0f;

    const int ncopy = (pass == 1) ? 2048 : 3072;
    auto copy_chunk = [&](int ch, int s) {
        const int k0c = ch * 32;
        const uint32_t sb = smem_base + s * STAGE_BYTES;
        for (int i = tid; i < ncopy; i += 256) {
            int sel  = i >> 9;
            int slot = (pass == 1) ? (sel + (sel & 2)) : sel;   // p1: 0,1,4,5
            int seg  = i & 511;
            int r    = seg >> 2;
            int c16  = seg & 3;
            const __nv_bfloat16* src;
            switch (slot) {
                case 0:  src = pM0; break;
                case 1:  src = pM1; break;
                case 2:  src = pM2; break;
                case 3:  src = pM3; break;
                case 4:  src = (r < 64) ? pBh0 : pBh1; break;
                default: src = (r < 64) ? pBl0 : pBl1; break;
            }
            uint32_t off = (uint32_t)(r * 64 + c16 * 16);
            uint32_t sw  = off ^ ((off >> 3) & 0x30);   // SW64
            CP_ASYNC_16(sb + slot * MAT_BYTES + sw, src + (size_t)r * NH + k0c + c16 * 8);
        }
    };

    // ldmatrix lane geometry (SW64, 64B rows)
    const int arow = wm * 32 + (lane & 15);
    const int acol = lane >> 4;
    const int brow = wn * 64 + (lane & 7) + ((lane >> 4) << 3);
    const int bcol = (lane >> 3) & 1;
    const uint32_t ab = (pass == 2 && wn) ? 2u * MAT_BYTES : 0u;  // A slot select

    copy_chunk(0, 0); CP_COMMIT();

    for (int ch = 0; ch < NCHUNK; ch++) {
        const int s = ch & 1;
        if (ch < NCHUNK - 1) {
            copy_chunk(ch + 1, s ^ 1);
            CP_COMMIT();
            CP_WAIT(1);
        } else {
            CP_WAIT(0);
        }
        __syncthreads();

        const uint32_t sb = smem_base + s * STAGE_BYTES;
#pragma unroll
        for (int j = 0; j < 2; j++) {
            uint32_t ah[2][4], al[2][4];
#pragma unroll
            for (int t = 0; t < 2; t++) {
                uint32_t off = (uint32_t)((arow + t * 16) * 64 + (acol + j * 2) * 16);
                uint32_t sw  = off ^ ((off >> 3) & 0x30);
                ldsm4(ah[t], sb + ab + sw);
                ldsm4(al[t], sb + ab + MAT_BYTES + sw);
            }
#pragma unroll
            for (int q = 0; q < 4; q++) {
                uint32_t bh[4], bl[4];
                uint32_t off = (uint32_t)((brow + q * 16) * 64 + (bcol + j * 2) * 16);
                uint32_t sw  = off ^ ((off >> 3) & 0x30);
                ldsm4(bh, sb + 4 * MAT_BYTES + sw);
                ldsm4(bl, sb + 5 * MAT_BYTES + sw);
#pragma unroll
                for (int t = 0; t < 2; t++)
#pragma unroll
                    for (int h = 0; h < 2; h++) {
                        int nt = q * 2 + h;
                        mma16816(acc[t][nt], ah[t], bh[h * 2], bh[h * 2 + 1]); // hi*hi
                        mma16816(acc[t][nt], ah[t], bl[h * 2], bl[h * 2 + 1]); // hi*lo
                        mma16816(acc[t][nt], al[t], bh[h * 2], bh[h * 2 + 1]); // lo*hi
                    }
            }
        }
        __syncthreads();   // stage s must drain before it is refilled
    }

    // ---- epilogue: fragments -> fp32 smem (stride 132) -> global ----
    const int er = lane >> 2;
    const int ec = (lane & 3) * 2;
    float* ef = (float*)smem;
#pragma unroll
    for (int t = 0; t < 2; t++)
#pragma unroll
        for (int nt = 0; nt < 8; nt++) {
            int row = wm * 32 + t * 16 + er;
#pragma unroll
            for (int hlf = 0; hlf < 2; hlf++) {
                float f0 = acc[t][nt][hlf * 2 + 0];
                float f1 = acc[t][nt][hlf * 2 + 1];
                int rr = (row + hlf * 8) * 132;
                if (pass == 1) {
                    int col = wn * 64 + nt * 8 + ec;
                    *(float2*)&ef[rr + col] = make_float2(f0, f1);
                } else {
                    int col = 2 * (nt * 8 + ec) + wn;   // interleave parities
                    ef[rr + col]     = f0;
                    ef[rr + col + 2] = f1;
                }
            }
        }
    __syncthreads();

    const int r = tid >> 1, half = tid & 1;
    if (pass == 1) {
        // t_perm row k' = parity*256 + m0 + r, contiguous 512-wide fp32 rows
        float* dst = g_t + (((size_t)p * NN) + (parity * 256 + m0 + r)) * NN + n0 + half * 64;
#pragma unroll
        for (int j = 0; j < 16; j++)
            *(float4*)(dst + j * 4) = *(const float4*)(ef + r * 132 + half * 64 + j * 4);
    } else {
        const int kp = m0 + r;                       // permuted k index
        const int k  = (kp < 256) ? 2 * kp : 2 * kp - 511;
        const int b = p / 3, c = p % 3;
        const int l0 = 2 * n0;
        float* dst = Out + (((size_t)b * NN + k) * NN + l0 + half * 64) * 3 + c;
#pragma unroll 8
        for (int j = 0; j < 64; j++)
            dst[j * 3] = ef[r * 132 + half * 64 + j];
    }
}

// ---------------- launcher ----------------
extern "C" void kernel_launch(void* const* d_in, const int* in_sizes, int n_in,
                              void* d_out, int out_size) {
    (void)in_sizes; (void)n_in; (void)out_size;
    const float* x = (const float*)d_in[0];
    float* out = (float*)d_out;

    cudaFuncSetAttribute(gemm_hmma_kernel,
                         cudaFuncAttributeMaxDynamicSharedMemorySize, GEMM_SMEM_TOTAL);

    init_dct_half<<<256, 256>>>();
    fold_split_x<<<dim3(16, 8, NB), 256>>>(x);

    gemm_hmma_kernel<<<dim3(4, 4, NPLANES), 256, GEMM_SMEM_TOTAL>>>(nullptr, 1);
    fold_split_t<<<12288, 256>>>();
    gemm_hmma_kernel<<<dim3(4, 4, NPLANES), 256, GEMM_SMEM_TOTAL>>>(out, 2);
}

// round 10
// speedup vs baseline: 4.3998x; 1.8273x over previous
#include <cuda_runtime.h>
#include <cuda_fp16.h>
#include <cstdint>
#include <math.h>

#define NB 32
#define NN 512
#define NH 256
#define NPLANES 96
#define HALF ((size_t)NN * NH)   // 512*256

// ---------------- device globals (no allocation allowed) ----------------
// DCT matrices stored x16 (pure cosines; row0 of De has the 1/sqrt2): fp16 hi/lo split
__device__ __align__(1024) __half g_De_h[NH * NH], g_De_l[NH * NH]; // even-k rows
__device__ __align__(1024) __half g_Do_h[NH * NH], g_Do_l[NH * NH]; // odd-k rows
// folded input, single-rounded fp16: [p=3b+c][w][h']
__device__ __align__(1024) __half g_xe[NPLANES * HALF], g_xo[NPLANES * HALF];
// pass-1 intermediate (scaled x16), fp32, permuted rows [p][k'][w]
__device__ __align__(1024) float  g_t[NPLANES * (size_t)NN * NN];
// folded intermediate, single-rounded fp16: [p][k'][w']
__device__ __align__(1024) __half g_te[NPLANES * HALF], g_to[NPLANES * HALF];

// ---------------- helpers ----------------
__device__ __forceinline__ uint32_t smem_to_u32(const void* smem_ptr) {
    uint32_t addr;
    asm("{ .reg .u64 tmp; cvta.to.shared.u64 tmp, %1; cvt.u32.u64 %0, tmp; }"
        : "=r"(addr) : "l"(smem_ptr));
    return addr;
}
#define CP_ASYNC_16(saddr, gptr) \
    asm volatile("cp.async.cg.shared.global [%0], [%1], 16;" \
        :: "r"((uint32_t)(saddr)), "l"(gptr) : "memory")
#define CP_COMMIT() asm volatile("cp.async.commit_group;" ::: "memory")
#define CP_WAIT(n)  asm volatile("cp.async.wait_group %0;" :: "n"(n) : "memory")

__device__ __forceinline__ void ldsm4(uint32_t r[4], uint32_t addr) {
    asm volatile("ldmatrix.sync.aligned.m8n8.x4.shared.b16 {%0,%1,%2,%3}, [%4];"
        : "=r"(r[0]), "=r"(r[1]), "=r"(r[2]), "=r"(r[3]) : "r"(addr));
}
__device__ __forceinline__ void mma16816(float c[4], const uint32_t a[4],
                                         uint32_t b0, uint32_t b1) {
    asm volatile(
        "mma.sync.aligned.m16n8k16.row.col.f32.f16.f16.f32 "
        "{%0,%1,%2,%3}, {%4,%5,%6,%7}, {%8,%9}, {%0,%1,%2,%3};"
        : "+f"(c[0]), "+f"(c[1]), "+f"(c[2]), "+f"(c[3])
        : "r"(a[0]), "r"(a[1]), "r"(a[2]), "r"(a[3]), "r"(b0), "r"(b1));
}
__device__ __forceinline__ void fp16split(float f, __half& h, __half& l) {
    h = __float2half(f);
    l = __float2half(f - __half2float(h));
}

// -------- kernel 0: half-size DCT matrices (x16 scale), fp16 hi/lo --------
__global__ void init_dct_half() {
    int idx = blockIdx.x * blockDim.x + threadIdx.x;   // 256*256 threads
    int r = idx >> 8;
    int h = idx & 255;
    int me = ((2 * h + 1) * (2 * r)) & 2047;
    float ve = cospif((float)me * (1.0f / 1024.0f));
    if (r == 0) ve *= 0.70710678118654752440f;
    fp16split(ve, g_De_h[idx], g_De_l[idx]);
    int mo = ((2 * h + 1) * (2 * r + 1)) & 2047;
    float vo = cospif((float)mo * (1.0f / 1024.0f));
    fp16split(vo, g_Do_h[idx], g_Do_l[idx]);
}

// -------- kernel 1: de-interleave + transpose + h-fold + single fp16 round --------
// x[b][h][w][c] fp32 -> xe/xo fp16 [p=3b+c][w][h'<256]
__global__ __launch_bounds__(256) void fold_split_x(const float* __restrict__ x) {
    __shared__ float tA[3][32][33];
    __shared__ float tB[3][32][33];
    const int tid = threadIdx.x;
    const int b = blockIdx.z, h0 = blockIdx.y * 32, w0 = blockIdx.x * 32;
    const float* baseA = x + (((size_t)b * NN + h0) * NN + w0) * 3;
    const float* baseB = x + (((size_t)b * NN + (480 - h0)) * NN + w0) * 3;

    for (int i = tid; i < 768; i += 256) {             // 32 rows x 24 float4
        int row = i / 24, f4 = i % 24;
        float4 va = *(const float4*)(baseA + (size_t)row * NN * 3 + f4 * 4);
        float4 vb = *(const float4*)(baseB + (size_t)row * NN * 3 + f4 * 4);
        int f = f4 * 4;
        tA[(f + 0) % 3][(f + 0) / 3][row] = va.x;
        tA[(f + 1) % 3][(f + 1) / 3][row] = va.y;
        tA[(f + 2) % 3][(f + 2) / 3][row] = va.z;
        tA[(f + 3) % 3][(f + 3) / 3][row] = va.w;
        tB[(f + 0) % 3][(f + 0) / 3][row] = vb.x;
        tB[(f + 1) % 3][(f + 1) / 3][row] = vb.y;
        tB[(f + 2) % 3][(f + 2) / 3][row] = vb.z;
        tB[(f + 3) % 3][(f + 3) / 3][row] = vb.w;
    }
    __syncthreads();

    const int wl = tid >> 3;
    const int hs = (tid & 7) * 4;
#pragma unroll
    for (int c = 0; c < 3; c++) {
        size_t p = (size_t)(b * 3 + c);
        size_t dst = (p * NN + (w0 + wl)) * NH + h0 + hs;
        union { __half v[4]; uint2 u; } ue, uo;
#pragma unroll
        for (int j = 0; j < 4; j++) {
            int hr = hs + j;
            float a = tA[c][wl][hr];
            float m = tB[c][wl][31 - hr];     // x[511-(h0+hr)]
            ue.v[j] = __float2half(a + m);
            uo.v[j] = __float2half(a - m);
        }
        *(uint2*)&g_xe[dst] = ue.u;
        *(uint2*)&g_xo[dst] = uo.u;
    }
}

// -------- kernel 3: w-fold of intermediate t, single fp16 round --------
__global__ __launch_bounds__(256) void fold_split_t() {
    int idx = blockIdx.x * 256 + threadIdx.x;   // 96*512*64 items
    int row = idx >> 6;                          // p*512 + k'
    int q = idx & 63;
    const float* src = g_t + (size_t)row * NN;
    float4 f = *(const float4*)(src + 4 * q);
    float4 g = *(const float4*)(src + 508 - 4 * q);
    float mv[4] = {g.w, g.z, g.y, g.x};
    float fv[4] = {f.x, f.y, f.z, f.w};
    union { __half v[4]; uint2 u; } ue, uo;
#pragma unroll
    for (int j = 0; j < 4; j++) {
        ue.v[j] = __float2half(fv[j] + mv[j]);
        uo.v[j] = __float2half(fv[j] - mv[j]);
    }
    size_t dst = (size_t)row * NH + 4 * q;
    *(uint2*)&g_te[dst] = ue.u;
    *(uint2*)&g_to[dst] = uo.u;
}

// ---------------- HMMA GEMM, K=256, 2-product one-sided fp16 split ----------------
// PASS 1: t_perm[k'][w] = (Deh+Del / Doh+Dol) @ xe/xo   -> fp32 (x16 scale)
// PASS 2: out = (te/to) @ (Deh+Del / Doh+Dol)^T, parity-interleaved, x(1/256)
// stage slots (8KB each, 128 rows x 64B, SW64):
//   PASS1: 0=Mat_h 1=Mat_l 2=X      PASS2: 0=te 1=to 2=B_h(De|Do) 3=B_l(De|Do)
#define MAT_BYTES   8192
#define STAGE_BYTES 32768
#define NCHUNK      8
#define GEMM_SMEM_TOTAL 69632   // max(2 stages = 64KB, epilogue 128*132*4 = 66KB)

template <int PASS>
__global__ __launch_bounds__(256, 2)
void gemm_hmma_kernel(float* __restrict__ Out) {
    extern __shared__ char smem[];
    const uint32_t smem_base = smem_to_u32(smem);
    const int tid  = threadIdx.x;
    const int wid  = tid >> 5;
    const int lane = tid & 31;
    const int p  = blockIdx.z;

    const __half *pA0, *pA1, *pB0, *pB1, *pB0b, *pB1b;
    int m0, n0, parity = 0;
    if (PASS == 1) {
        parity = blockIdx.y >> 1;
        m0 = (blockIdx.y & 1) * 128;
        n0 = blockIdx.x * 128;
        pA0 = (parity ? g_Do_h : g_De_h) + (size_t)m0 * NH;   // slot0: matrix hi
        pA1 = (parity ? g_Do_l : g_De_l) + (size_t)m0 * NH;   // slot1: matrix lo
        pB0 = (parity ? g_xo : g_xe) + (size_t)p * HALF + (size_t)n0 * NH; // slot2: data
        pB1 = pB0; pB0b = pB0; pB1b = pB0;
    } else {
        m0 = blockIdx.y * 128;                  // k' tile
        n0 = blockIdx.x * 64;                   // l'' offset (final l tile = 2*n0)
        pA0 = g_te + (size_t)p * HALF + (size_t)m0 * NH;      // slot0: even data
        pA1 = g_to + (size_t)p * HALF + (size_t)m0 * NH;      // slot1: odd data
        pB0  = g_De_h + (size_t)n0 * NH;                      // slot2 rows 0..63
        pB0b = g_Do_h + ((long long)n0 - 64) * NH;            // slot2 rows 64..127
        pB1  = g_De_l + (size_t)n0 * NH;                      // slot3 rows 0..63
        pB1b = g_Do_l + ((long long)n0 - 64) * NH;            // slot3 rows 64..127
    }

    const int wm = wid & 3;
    const int wn = wid >> 2;

    float acc[2][8][4];
#pragma unroll
    for (int t = 0; t < 2; t++)
#pragma unroll
        for (int nt = 0; nt < 8; nt++)
#pragma unroll
            for (int r = 0; r < 4; r++) acc[t][nt][r] = 0.0f;

    const int ncopy = (PASS == 1) ? 1536 : 2048;
    auto copy_chunk = [&](int ch, int s) {
        const int k0c = ch * 32;
        const uint32_t sb = smem_base + s * STAGE_BYTES;
        for (int i = tid; i < ncopy; i += 256) {
            int slot = i >> 9;
            int seg  = i & 511;
            int r    = seg >> 2;
            int c16  = seg & 3;
            const __half* src;
            switch (slot) {
                case 0:  src = pA0; break;
                case 1:  src = pA1; break;
                case 2:  src = (PASS == 1) ? pB0 : ((r < 64) ? pB0 : pB0b); break;
                default: src = (r < 64) ? pB1 : pB1b; break;
            }
            uint32_t off = (uint32_t)(r * 64 + c16 * 16);
            uint32_t sw  = off ^ ((off >> 3) & 0x30);   // SW64
            CP_ASYNC_16(sb + slot * MAT_BYTES + sw, src + (size_t)r * NH + k0c + c16 * 8);
        }
    };

    // ldmatrix lane geometry (SW64, 64B rows)
    const int arow = wm * 32 + (lane & 15);
    const int acol = lane >> 4;
    const int brow = wn * 64 + (lane & 7) + ((lane >> 4) << 3);
    const int bcol = (lane >> 3) & 1;
    const uint32_t abase = (PASS == 2 && wn) ? (uint32_t)MAT_BYTES : 0u;

    copy_chunk(0, 0); CP_COMMIT();

    for (int ch = 0; ch < NCHUNK; ch++) {
        const int s = ch & 1;
        if (ch < NCHUNK - 1) {
            copy_chunk(ch + 1, s ^ 1);
            CP_COMMIT();
            CP_WAIT(1);
        } else {
            CP_WAIT(0);
        }
        __syncthreads();

        const uint32_t sb = smem_base + s * STAGE_BYTES;
#pragma unroll
        for (int j = 0; j < 2; j++) {
            uint32_t a0[2][4], a1[2][4];
#pragma unroll
            for (int t = 0; t < 2; t++) {
                uint32_t off = (uint32_t)((arow + t * 16) * 64 + (acol + j * 2) * 16);
                uint32_t sw  = off ^ ((off >> 3) & 0x30);
                if (PASS == 1) {
                    ldsm4(a0[t], sb + sw);               // matrix hi
                    ldsm4(a1[t], sb + MAT_BYTES + sw);   // matrix lo
                } else {
                    ldsm4(a0[t], sb + abase + sw);       // te or to
                }
            }
#pragma unroll
            for (int q = 0; q < 4; q++) {
                uint32_t off = (uint32_t)((brow + q * 16) * 64 + (bcol + j * 2) * 16);
                uint32_t sw  = off ^ ((off >> 3) & 0x30);
                if (PASS == 1) {
                    uint32_t b[4];
                    ldsm4(b, sb + 2 * MAT_BYTES + sw);
#pragma unroll
                    for (int t = 0; t < 2; t++)
#pragma unroll
                        for (int h = 0; h < 2; h++) {
                            int nt = q * 2 + h;
                            mma16816(acc[t][nt], a0[t], b[h * 2], b[h * 2 + 1]); // hi*x
                            mma16816(acc[t][nt], a1[t], b[h * 2], b[h * 2 + 1]); // lo*x
                        }
                } else {
                    uint32_t bh[4], bl[4];
                    ldsm4(bh, sb + 2 * MAT_BYTES + sw);
                    ldsm4(bl, sb + 3 * MAT_BYTES + sw);
#pragma unroll
                    for (int t = 0; t < 2; t++)
#pragma unroll
                        for (int h = 0; h < 2; h++) {
                            int nt = q * 2 + h;
                            mma16816(acc[t][nt], a0[t], bh[h * 2], bh[h * 2 + 1]); // t*hi
                            mma16816(acc[t][nt], a0[t], bl[h * 2], bl[h * 2 + 1]); // t*lo
                        }
                }
            }
        }
        __syncthreads();   // stage s must drain before it is refilled
    }

    // ---- epilogue: fragments -> fp32 smem (stride 132) -> global ----
    const int er = lane >> 2;
    const int ec = (lane & 3) * 2;
    float* ef = (float*)smem;
#pragma unroll
    for (int t = 0; t < 2; t++)
#pragma unroll
        for (int nt = 0; nt < 8; nt++) {
            int row = wm * 32 + t * 16 + er;
#pragma unroll
            for (int hlf = 0; hlf < 2; hlf++) {
                float f0 = acc[t][nt][hlf * 2 + 0];
                float f1 = acc[t][nt][hlf * 2 + 1];
                int rr = (row + hlf * 8) * 132;
                if (PASS == 1) {
                    int col = wn * 64 + nt * 8 + ec;
                    *(float2*)&ef[rr + col] = make_float2(f0, f1);
                } else {
                    int col = 2 * (nt * 8 + ec) + wn;   // interleave parities
                    ef[rr + col]     = f0 * 0.00390625f;   // 1/256 scale fixup
                    ef[rr + col + 2] = f1 * 0.00390625f;
                }
            }
        }
    __syncthreads();

    const int r = tid >> 1, half = tid & 1;
    if (PASS == 1) {
        float* dst = g_t + (((size_t)p * NN) + (parity * 256 + m0 + r)) * NN + n0 + half * 64;
#pragma unroll
        for (int j = 0; j < 16; j++)
            *(float4*)(dst + j * 4) = *(const float4*)(ef + r * 132 + half * 64 + j * 4);
    } else {
        const int kp = m0 + r;                       // permuted k index
        const int k  = (kp < 256) ? 2 * kp : 2 * kp - 511;
        const int b = p / 3, c = p % 3;
        const int l0 = 2 * n0;
        float* dst = Out + (((size_t)b * NN + k) * NN + l0 + half * 64) * 3 + c;
#pragma unroll 8
        for (int j = 0; j < 64; j++)
            dst[j * 3] = ef[r * 132 + half * 64 + j];
    }
}

// ---------------- launcher ----------------
extern "C" void kernel_launch(void* const* d_in, const int* in_sizes, int n_in,
                              void* d_out, int out_size) {
    (void)in_sizes; (void)n_in; (void)out_size;
    const float* x = (const float*)d_in[0];
    float* out = (float*)d_out;

    cudaFuncSetAttribute(gemm_hmma_kernel<1>,
                         cudaFuncAttributeMaxDynamicSharedMemorySize, GEMM_SMEM_TOTAL);
    cudaFuncSetAttribute(gemm_hmma_kernel<2>,
                         cudaFuncAttributeMaxDynamicSharedMemorySize, GEMM_SMEM_TOTAL);

    init_dct_half<<<256, 256>>>();
    fold_split_x<<<dim3(16, 8, NB), 256>>>(x);

    gemm_hmma_kernel<1><<<dim3(4, 4, NPLANES), 256, GEMM_SMEM_TOTAL>>>(nullptr);
    fold_split_t<<<12288, 256>>>();
    gemm_hmma_kernel<2><<<dim3(4, 4, NPLANES), 256, GEMM_SMEM_TOTAL>>>(out);
}